// round 15
// baseline (speedup 1.0000x reference)
#include <cuda_runtime.h>

#define NB     16
#define NCLS   20
#define NPM    27280          // anchors per modality (div by 4)
#define NPB    (2*NPM)        // 54560 anchors per batch
#define NGRP   (NPB/4)        // 13640 anchor-groups per batch
#define TOTAL  (NB*NPB)       // 872960
#define MAXD   1000
#define NPAD   1024
#define MASKW  16             // 1024 bits -> 16 u64 words
#define TOPN   (NB*MAXD)      // 16000
#define HBINS  8192
#define BINOFF 121856         // (0x3F800000>>13) - 8192
#define CAP    4096
#define NTILES 40             // live upper-triangle (i-tile, j-group) pairs
#define GBLK   125            // gather blocks per batch (8 dets each)

typedef unsigned long long u64;

struct Ptrs { const float* p[30]; };

// live (xt, yg) pairs with 4*yg+3 >= xt
__device__ __constant__ unsigned char c_tile_xt[NTILES] = {
    0,0,0,0, 1,1,1,1, 2,2,2,2, 3,3,3,3,
    4,4,4, 5,5,5, 6,6,6, 7,7,7,
    8,8, 9,9, 10,10, 11,11,
    12, 13, 14, 15 };
__device__ __constant__ unsigned char c_tile_yg[NTILES] = {
    0,1,2,3, 0,1,2,3, 0,1,2,3, 0,1,2,3,
    1,2,3, 1,2,3, 1,2,3, 1,2,3,
    2,3, 2,3, 2,3, 2,3,
    3, 3, 3, 3 };

// ---- static device scratch (no allocations; statics zero-init) ----
__device__ unsigned int g_scores[TOTAL];
__device__ int          g_hist[NB*HBINS];     // zeroed in k_rank prologue each run
__device__ int          g_ccount[NB];         // reset in k_gather
__device__ u64          g_cand[NB*CAP];
__device__ u64          g_topkeys[TOPN];
__device__ float        g_top_s[TOPN];
__device__ int          g_top_c[TOPN];
__device__ float        g_top_b[TOPN*4];
__device__ unsigned char g_valid[TOPN];
__device__ float        g_blkmax[NB*GBLK];
__device__ __align__(16) u64 g_mask[(size_t)NB*NPAD*MASKW];

// sigmoid exactly as passing rounds (rel_err 1.3e-8) — do not change
__device__ __forceinline__ float sigm(float x){
    return __fdiv_rn(1.0f, __fadd_rn(1.0f, expf(-x)));
}

__device__ __forceinline__ int score_bin(unsigned int bits){
    int v = (int)(bits >> 13) - BINOFF;
    return max(0, min(HBINS-1, v));
}

__device__ __forceinline__ void locate(int m, int& lvl, int& pos, int& w, int& st, int& hw){
    if (m < 20480)      { lvl=0; pos=m;        w=160; st=8;   hw=20480; }
    else if (m < 25600) { lvl=1; pos=m-20480;  w=80;  st=16;  hw=5120;  }
    else if (m < 26880) { lvl=2; pos=m-25600;  w=40;  st=32;  hw=1280;  }
    else if (m < 27200) { lvl=3; pos=m-26880;  w=20;  st=64;  hw=320;   }
    else                { lvl=4; pos=m-27200;  w=10;  st=128; hw=80;    }
}

// ---- 1. decode (float4) + per-batch smem histogram; PDL trigger at top ----
__global__ __launch_bounds__(256) void k_decode(Ptrs P){
    cudaTriggerProgrammaticLaunchCompletion();     // let compact's launch overlap us
    __shared__ int sh[HBINS];
    int b = blockIdx.y;
    for (int i = threadIdx.x; i < HBINS; i += 256) sh[i] = 0;
    __syncthreads();
    int g = blockIdx.x*256 + threadIdx.x;
    if (g < NGRP){
        int n = g*4;
        int mod = (n >= NPM) ? 1 : 0;
        int m   = n - mod*NPM;
        int lvl,pos,w,st,hw; locate(m,lvl,pos,w,st,hw);
        const float4* __restrict__ cls4 = (const float4*)P.p[mod*15 + lvl];
        const float4* __restrict__ cnt4 = (const float4*)P.p[mod*15 + 5 + lvl];
        int hw4 = hw >> 2, p4 = pos >> 2;
        int cbase = b*NCLS*hw4 + p4;
        float4 lm = cls4[cbase];
        #pragma unroll
        for (int c=1;c<NCLS;c++){
            float4 v = cls4[cbase + c*hw4];
            lm.x = fmaxf(lm.x, v.x); lm.y = fmaxf(lm.y, v.y);
            lm.z = fmaxf(lm.z, v.z); lm.w = fmaxf(lm.w, v.w);
        }
        float4 qv = cnt4[b*hw4 + p4];
        float lmv[4] = {lm.x, lm.y, lm.z, lm.w};
        float qvv[4] = {qv.x, qv.y, qv.z, qv.w};
        unsigned int sb[4];
        #pragma unroll
        for (int j=0;j<4;j++){
            float pmax = sigm(lmv[j]);                 // max_c sigm == sigm(max_c)
            float q = sigm(qvv[j]);
            float score = __fsqrt_rn(__fmul_rn(pmax, q));
            sb[j] = __float_as_uint(score);
            atomicAdd(&sh[score_bin(sb[j])], 1);
        }
        *(uint4*)&g_scores[b*NPB + n] = make_uint4(sb[0],sb[1],sb[2],sb[3]);
    }
    __syncthreads();
    for (int i = threadIdx.x; i < HBINS; i += 256){
        int v = sh[i];
        if (v) atomicAdd(&g_hist[b*HBINS + i], v);
    }
}

// ---- 2. compact (+in-block redundant threshold) ----
__global__ __launch_bounds__(256) void k_compact(){
    cudaGridDependencySynchronize();               // wait decode completion
    cudaTriggerProgrammaticLaunchCompletion();
    __shared__ int gsum[256];
    __shared__ int sT;
    int b = blockIdx.y, tid = threadIdx.x;
    const int* h = &g_hist[b*HBINS];
    int s = 0;
    #pragma unroll 8
    for (int k = 0; k < 32; k++) s += h[tid*32 + k];
    gsum[tid] = s;
    __syncthreads();
    if (tid == 0){
        int acc = 0, g = 255;
        while (g > 0 && acc + gsum[g] < MAXD){ acc += gsum[g]; g--; }
        int T = g*32;
        for (int k = 31; k >= 0; k--){
            acc += h[g*32 + k];
            if (acc >= MAXD){ T = g*32 + k; break; }
        }
        sT = T;
    }
    __syncthreads();
    int T = sT;
    int base = blockIdx.x * 2048;
    #pragma unroll
    for (int r = 0; r < 8; r++){
        int n = base + r*256 + tid;
        if (n < NPB){
            unsigned int sb = g_scores[b*NPB + n];
            if (score_bin(sb) >= T){
                int slot = atomicAdd(&g_ccount[b], 1);
                if (slot < CAP)
                    g_cand[b*CAP + slot] =
                        ((u64)sb << 28) | (u64)(0x0FFFFFFFu - (unsigned)n);
            }
        }
    }
}

// ---- 3. rank by enumeration; hist zero AFTER sync (compact reads hist) ----
__global__ __launch_bounds__(256) void k_rank(){
    cudaGridDependencySynchronize();               // wait compact completion
    cudaTriggerProgrammaticLaunchCompletion();
    int zid = (blockIdx.y*gridDim.x + blockIdx.x)*256 + threadIdx.x;
    for (int i = zid; i < NB*HBINS; i += gridDim.x*gridDim.y*256) g_hist[i] = 0;
    int b = blockIdx.y;
    int C = min(g_ccount[b], CAP);
    if (blockIdx.x*256 >= C) return;
    int idx = blockIdx.x*256 + threadIdx.x;
    u64 my = (idx < C) ? g_cand[b*CAP + idx] : 0ull;
    int rank = 0;
    __shared__ u64 tile[256];
    for (int t0 = 0; t0 < C; t0 += 256){
        int j = t0 + threadIdx.x;
        tile[threadIdx.x] = (j < C) ? g_cand[b*CAP + j] : 0ull;
        __syncthreads();
        int tn = min(256, C - t0);
        #pragma unroll 8
        for (int k = 0; k < tn; k++) rank += (tile[k] > my) ? 1 : 0;
        __syncthreads();
    }
    if (idx < C && rank < MAXD) g_topkeys[b*MAXD + rank] = my;
}

// ---- 4. gather: one WARP per detection; ccount reset AFTER sync ----
__global__ __launch_bounds__(256) void k_gather(Ptrs P){
    cudaGridDependencySynchronize();               // wait rank completion
    cudaTriggerProgrammaticLaunchCompletion();
    int cr = blockIdx.x, b = blockIdx.y, tid = threadIdx.x;
    int wid = tid >> 5, lane = tid & 31;
    if (cr == 0 && tid == 0) g_ccount[b] = 0;      // reset for next replay
    __shared__ float wmax[8];
    int j = cr*8 + wid;                            // det index in batch (< 1000)
    int t = b*MAXD + j;
    u64 key = g_topkeys[t];
    float score = __uint_as_float((unsigned int)(key >> 28));
    int n = 0x0FFFFFFF - (int)(key & 0x0FFFFFFFull);
    int mod = (n >= NPM) ? 1 : 0;
    int m = n - mod*NPM;
    int lvl,pos,w,st,hw; locate(m,lvl,pos,w,st,hw);
    const float* cls = P.p[mod*15 + lvl];
    const float* reg = P.p[mod*15 + 10 + lvl];
    int cbase = b*NCLS*hw + pos;
    int rbase = b*4*hw + pos;
    float sv = (lane < NCLS) ? sigm(cls[cbase + lane*hw]) : -INFINITY;
    float rv = (lane >= 20 && lane < 24) ? reg[rbase + (lane-20)*hw] : 0.0f;
    // lexicographic max (value, -index): == first-occurrence argmax
    float s = sv; int idx = lane;
    #pragma unroll
    for (int off = 16; off > 0; off >>= 1){
        float s2 = __shfl_down_sync(0xffffffffu, s, off);
        int   i2 = __shfl_down_sync(0xffffffffu, idx, off);
        if (s2 > s || (s2 == s && i2 < idx)){ s = s2; idx = i2; }
    }
    float r0 = __shfl_sync(0xffffffffu, rv, 20);
    float r1 = __shfl_sync(0xffffffffu, rv, 21);
    float r2 = __shfl_sync(0xffffffffu, rv, 22);
    float r3 = __shfl_sync(0xffffffffu, rv, 23);
    if (lane == 0){
        int y = pos / w, x = pos - y*w;
        float fx = (float)(x*st + (st>>1));
        float fy = (float)(y*st + (st>>1));
        float bx0 = __fsub_rn(fx, r0);
        float bx1 = __fsub_rn(fy, r1);
        float bx2 = __fadd_rn(fx, r2);
        float bx3 = __fadd_rn(fy, r3);
        int cl = idx + 1;
        unsigned char vl = (score >= 0.05f) ? 1 : 0;
        g_top_s[t] = score;
        g_top_c[t] = cl;
        g_top_b[4*t+0]=bx0; g_top_b[4*t+1]=bx1;
        g_top_b[4*t+2]=bx2; g_top_b[4*t+3]=bx3;
        g_valid[t] = vl;
        wmax[wid] = vl ? fmaxf(fmaxf(bx0,bx1), fmaxf(bx2,bx3)) : 0.0f;
    }
    __syncthreads();
    if (tid == 0){
        float mx = wmax[0];
        #pragma unroll
        for (int q = 1; q < 8; q++) mx = fmaxf(mx, wmax[q]);
        g_blkmax[b*GBLK + cr] = mx;
    }
}

// ---- 5. IoU mask with on-the-fly class offset (bit-identical op sequence) ----
__global__ __launch_bounds__(256) void k_mask(){
    cudaGridDependencySynchronize();               // wait gather completion
    cudaTriggerProgrammaticLaunchCompletion();
    int xt = c_tile_xt[blockIdx.x];
    int yg = c_tile_yg[blockIdx.x];
    int b  = blockIdx.y;
    __shared__ float sx1[256],sy1[256],sx2[256],sy2[256],sa[256];
    float mm = g_blkmax[b*GBLK];
    #pragma unroll 5
    for (int q = 1; q < GBLK; q++) mm = fmaxf(mm, g_blkmax[b*GBLK + q]);
    float mc1 = __fadd_rn(mm, 1.0f);
    int jj = yg*256 + threadIdx.x;
    if (jj < MAXD){
        int tj = b*MAXD + jj;
        float off = __fmul_rn((float)g_top_c[tj], mc1);
        float x1 = __fadd_rn(g_top_b[4*tj+0], off);
        float y1 = __fadd_rn(g_top_b[4*tj+1], off);
        float x2 = __fadd_rn(g_top_b[4*tj+2], off);
        float y2 = __fadd_rn(g_top_b[4*tj+3], off);
        sx1[threadIdx.x]=x1; sy1[threadIdx.x]=y1;
        sx2[threadIdx.x]=x2; sy2[threadIdx.x]=y2;
        sa[threadIdx.x]=__fmul_rn(__fadd_rn(__fsub_rn(x2,x1),1.0f),
                                  __fadd_rn(__fsub_rn(y2,y1),1.0f));
    }
    __syncthreads();
    int il = threadIdx.x & 63;
    int wq = threadIdx.x >> 6;
    int i  = xt*64 + il;
    int w  = yg*4 + wq;
    if (i >= MAXD) return;
    if (w < (i >> 6)) return;
    int j0 = w*64;
    int jn = min(64, MAXD - j0);
    if (jn <= 0) return;
    int ti = b*MAXD + i;
    float offi = __fmul_rn((float)g_top_c[ti], mc1);
    float x1 = __fadd_rn(g_top_b[4*ti+0], offi);
    float y1 = __fadd_rn(g_top_b[4*ti+1], offi);
    float x2 = __fadd_rn(g_top_b[4*ti+2], offi);
    float y2 = __fadd_rn(g_top_b[4*ti+3], offi);
    float ai = __fmul_rn(__fadd_rn(__fsub_rn(x2,x1),1.0f),
                         __fadd_rn(__fsub_rn(y2,y1),1.0f));
    int sb = wq*64;
    u64 word = 0;
    for (int k=0;k<jn;k++){
        float xx1=fmaxf(x1,sx1[sb+k]), yy1=fmaxf(y1,sy1[sb+k]);
        float xx2=fminf(x2,sx2[sb+k]), yy2=fminf(y2,sy2[sb+k]);
        float iw=fmaxf(__fadd_rn(__fsub_rn(xx2,xx1),1.0f),0.0f);
        float ih=fmaxf(__fadd_rn(__fsub_rn(yy2,yy1),1.0f),0.0f);
        float inter=__fmul_rn(iw,ih);
        float denom=__fsub_rn(__fadd_rn(ai,sa[sb+k]),inter);
        float p = __fmul_rn(0.6f, denom);
        float e = __fmaf_rn(0.6f, denom, -p);                  // exact residual
        float s = __fadd_rn(e, __fmul_rn(0x1.0p-25f, denom));  // half-ulp shift
        float t = __fsub_rn(inter, p);
        bool sup;
        if (denom > 0.0f) sup = (t > s);
        else              sup = (denom == 0.0f && inter > 0.0f);
        if (sup) word |= (1ull<<k);
    }
    g_mask[((size_t)b*NPAD + i)*MASKW + w] = word;
}

// ---- 6. fused greedy scan + output write (NO early trigger: fences replay) ----
__global__ void k_scan_out(float* __restrict__ out){
    cudaGridDependencySynchronize();               // wait mask completion
    extern __shared__ u64 sm[];                    // NPAD*MASKW words
    __shared__ u64 svm[MASKW];
    __shared__ u64 skeep[MASKW];
    int b = blockIdx.x, tid = threadIdx.x;
    const ulonglong2* src2 = (const ulonglong2*)&g_mask[(size_t)b*NPAD*MASKW];
    ulonglong2* sm2 = (ulonglong2*)sm;
    for (int i = tid; i < NPAD*MASKW/2; i += blockDim.x){
        ulonglong2 v = (i < MAXD*MASKW/2) ? src2[i] : make_ulonglong2(0ull,0ull);
        sm2[i] = v;
    }
    if (tid < MASKW){
        u64 w = 0;
        for (int i = 0; i < 64; i++){
            int j = tid*64 + i;
            if (j < MAXD && g_valid[b*MAXD + j]) w |= 1ull << i;
        }
        svm[tid] = w;
    }
    __syncthreads();
    if (tid < 32){
        int lane = tid;
        u64 removed = 0;
        for (int c = 0; c < MASKW; c++){
            u64 sup = __shfl_sync(0xffffffffu, removed, c);
            u64 vmc = svm[c];
            u64 kd = 0;
            #pragma unroll
            for (int q = 0; q < 4; q++){
                u64 dreg[16];
                #pragma unroll
                for (int r = 0; r < 16; r++) dreg[r] = sm[(c*64 + q*16 + r)*MASKW + c];
                #pragma unroll
                for (int r = 0; r < 16; r++){
                    int i = q*16 + r;
                    bool k = ((vmc >> i) & 1ull) && !((sup >> i) & 1ull);
                    if (k){ kd |= 1ull << i; sup |= dreg[r]; }
                }
            }
            if (lane == c) skeep[c] = kd;
            if (lane < MASKW){
                #pragma unroll
                for (int i = 0; i < 64; i++)
                    if ((kd >> i) & 1ull)
                        removed |= sm[(size_t)(c*64 + i)*MASKW + lane];
            }
        }
    }
    __syncthreads();
    for (int j = tid; j < MAXD; j += blockDim.x){
        int t = b*MAXD + j;
        int keep = (int)((skeep[j >> 6] >> (j & 63)) & 1ull);
        float kf = keep ? 1.0f : 0.0f;
        out[t]        = __fmul_rn(g_top_s[t], kf);
        out[TOPN + t] = keep ? (float)g_top_c[t] : 0.0f;
        float x1 = fminf(fmaxf(g_top_b[4*t+0],0.0f),1279.0f);
        float y1 = fminf(fmaxf(g_top_b[4*t+1],0.0f),1023.0f);
        float x2 = fminf(fmaxf(g_top_b[4*t+2],0.0f),1279.0f);
        float y2 = fminf(fmaxf(g_top_b[4*t+3],0.0f),1023.0f);
        out[2*TOPN + 4*t+0]=__fmul_rn(x1,kf);
        out[2*TOPN + 4*t+1]=__fmul_rn(y1,kf);
        out[2*TOPN + 4*t+2]=__fmul_rn(x2,kf);
        out[2*TOPN + 4*t+3]=__fmul_rn(y2,kf);
        out[6*TOPN + t]=kf;
    }
}

// host helper: launch with PDL attribute, fall back to plain launch on error
template <typename K, typename... Args>
static void launch_pdl(K kern, dim3 grid, dim3 block, size_t smem, Args... args){
    cudaLaunchConfig_t cfg = {};
    cfg.gridDim = grid; cfg.blockDim = block;
    cfg.dynamicSmemBytes = smem; cfg.stream = 0;
    cudaLaunchAttribute attr[1];
    attr[0].id = cudaLaunchAttributeProgrammaticStreamSerialization;
    attr[0].val.programmaticStreamSerializationAllowed = 1;
    cfg.attrs = attr; cfg.numAttrs = 1;
    if (cudaLaunchKernelEx(&cfg, kern, args...) != cudaSuccess)
        kern<<<grid, block, smem>>>(args...);
}

extern "C" void kernel_launch(void* const* d_in, const int* in_sizes, int n_in,
                              void* d_out, int out_size){
    Ptrs P;
    for (int i=0;i<30;i++) P.p[i] = (const float*)d_in[i];

    const int scan_smem = NPAD*MASKW*8;   // 131072 bytes
    cudaFuncSetAttribute(k_scan_out, cudaFuncAttributeMaxDynamicSharedMemorySize, scan_smem);

    launch_pdl(k_decode,   dim3((NGRP + 255)/256, NB), dim3(256), 0, P);
    launch_pdl(k_compact,  dim3(27, NB),               dim3(256), 0);
    launch_pdl(k_rank,     dim3(CAP/256, NB),          dim3(256), 0);
    launch_pdl(k_gather,   dim3(GBLK, NB),             dim3(256), 0, P);
    launch_pdl(k_mask,     dim3(NTILES, NB),           dim3(256), 0);
    launch_pdl(k_scan_out, dim3(NB),                   dim3(256), (size_t)scan_smem, (float*)d_out);
}

// round 16
// speedup vs baseline: 1.1420x; 1.1420x over previous
#include <cuda_runtime.h>

#define NB     16
#define NCLS   20
#define NPM    27280          // anchors per modality (div by 8)
#define NPB    (2*NPM)        // 54560 anchors per batch
#define NOCT   (NPB/8)        // 6820 anchor-octets per batch
#define TOTAL  (NB*NPB)       // 872960
#define MAXD   1000
#define NPAD   1024
#define MASKW  16             // 1024 bits -> 16 u64 words
#define TOPN   (NB*MAXD)      // 16000
#define HBINS  8192
#define BINOFF 121856         // (0x3F800000>>13) - 8192
#define CAP    4096
#define NTILES 40             // live upper-triangle (i-tile, j-group) pairs
#define GBLK   125            // gather blocks per batch (8 dets each)

typedef unsigned long long u64;

struct Ptrs { const float* p[30]; };

// live (xt, yg) pairs with 4*yg+3 >= xt
__device__ __constant__ unsigned char c_tile_xt[NTILES] = {
    0,0,0,0, 1,1,1,1, 2,2,2,2, 3,3,3,3,
    4,4,4, 5,5,5, 6,6,6, 7,7,7,
    8,8, 9,9, 10,10, 11,11,
    12, 13, 14, 15 };
__device__ __constant__ unsigned char c_tile_yg[NTILES] = {
    0,1,2,3, 0,1,2,3, 0,1,2,3, 0,1,2,3,
    1,2,3, 1,2,3, 1,2,3, 1,2,3,
    2,3, 2,3, 2,3, 2,3,
    3, 3, 3, 3 };

// ---- static device scratch (no allocations; statics zero-init) ----
__device__ unsigned int g_scores[TOTAL];
__device__ int          g_hist[NB*HBINS];     // zeroed in k_rank prologue each run
__device__ int          g_ccount[NB];         // reset in k_gather
__device__ u64          g_cand[NB*CAP];
__device__ u64          g_topkeys[TOPN];
__device__ float        g_top_s[TOPN];
__device__ int          g_top_c[TOPN];
__device__ float        g_top_b[TOPN*4];
__device__ unsigned char g_valid[TOPN];
__device__ float        g_blkmax[NB*GBLK];
__device__ __align__(16) u64 g_mask[(size_t)NB*NPAD*MASKW];

// sigmoid exactly as passing rounds (rel_err 1.3e-8) — do not change
__device__ __forceinline__ float sigm(float x){
    return __fdiv_rn(1.0f, __fadd_rn(1.0f, expf(-x)));
}

__device__ __forceinline__ int score_bin(unsigned int bits){
    int v = (int)(bits >> 13) - BINOFF;
    return max(0, min(HBINS-1, v));
}

__device__ __forceinline__ void locate(int m, int& lvl, int& pos, int& w, int& st, int& hw){
    if (m < 20480)      { lvl=0; pos=m;        w=160; st=8;   hw=20480; }
    else if (m < 25600) { lvl=1; pos=m-20480;  w=80;  st=16;  hw=5120;  }
    else if (m < 26880) { lvl=2; pos=m-25600;  w=40;  st=32;  hw=1280;  }
    else if (m < 27200) { lvl=3; pos=m-26880;  w=20;  st=64;  hw=320;   }
    else                { lvl=4; pos=m-27200;  w=10;  st=128; hw=80;    }
}

// ---- 1. decode: 8 anchors/thread (2x float4) + per-batch smem histogram ----
// All (mod,lvl) boundaries divisible by 8 -> one locate() per octet.
__global__ __launch_bounds__(256) void k_decode(Ptrs P){
    __shared__ int sh[HBINS];
    int b = blockIdx.y;
    for (int i = threadIdx.x; i < HBINS; i += 256) sh[i] = 0;
    __syncthreads();
    int g = blockIdx.x*256 + threadIdx.x;
    if (g < NOCT){
        int n = g*8;
        int mod = (n >= NPM) ? 1 : 0;
        int m   = n - mod*NPM;
        int lvl,pos,w,st,hw; locate(m,lvl,pos,w,st,hw);
        const float4* __restrict__ cls4 = (const float4*)P.p[mod*15 + lvl];
        const float4* __restrict__ cnt4 = (const float4*)P.p[mod*15 + 5 + lvl];
        int hw4 = hw >> 2, p4 = pos >> 2;
        int cbase = b*NCLS*hw4 + p4;
        float4 lmA = cls4[cbase], lmB = cls4[cbase+1];
        #pragma unroll
        for (int c=1;c<NCLS;c++){
            float4 vA = cls4[cbase + c*hw4];
            float4 vB = cls4[cbase + c*hw4 + 1];
            lmA.x = fmaxf(lmA.x, vA.x); lmA.y = fmaxf(lmA.y, vA.y);
            lmA.z = fmaxf(lmA.z, vA.z); lmA.w = fmaxf(lmA.w, vA.w);
            lmB.x = fmaxf(lmB.x, vB.x); lmB.y = fmaxf(lmB.y, vB.y);
            lmB.z = fmaxf(lmB.z, vB.z); lmB.w = fmaxf(lmB.w, vB.w);
        }
        float4 qA = cnt4[b*hw4 + p4], qB = cnt4[b*hw4 + p4 + 1];
        float lmv[8] = {lmA.x,lmA.y,lmA.z,lmA.w, lmB.x,lmB.y,lmB.z,lmB.w};
        float qvv[8] = {qA.x,qA.y,qA.z,qA.w, qB.x,qB.y,qB.z,qB.w};
        unsigned int sb[8];
        #pragma unroll
        for (int j=0;j<8;j++){
            float pmax = sigm(lmv[j]);                 // max_c sigm == sigm(max_c)
            float q = sigm(qvv[j]);
            float score = __fsqrt_rn(__fmul_rn(pmax, q));
            sb[j] = __float_as_uint(score);
            atomicAdd(&sh[score_bin(sb[j])], 1);
        }
        *(uint4*)&g_scores[b*NPB + n]     = make_uint4(sb[0],sb[1],sb[2],sb[3]);
        *(uint4*)&g_scores[b*NPB + n + 4] = make_uint4(sb[4],sb[5],sb[6],sb[7]);
    }
    __syncthreads();
    for (int i = threadIdx.x; i < HBINS; i += 256){
        int v = sh[i];
        if (v) atomicAdd(&g_hist[b*HBINS + i], v);
    }
}

// ---- 2. compact (+in-block redundant threshold) ----
__global__ __launch_bounds__(256) void k_compact(){
    __shared__ int gsum[256];
    __shared__ int sT;
    int b = blockIdx.y, tid = threadIdx.x;
    const int* h = &g_hist[b*HBINS];
    int s = 0;
    #pragma unroll 8
    for (int k = 0; k < 32; k++) s += h[tid*32 + k];
    gsum[tid] = s;
    __syncthreads();
    if (tid == 0){
        int acc = 0, g = 255;
        while (g > 0 && acc + gsum[g] < MAXD){ acc += gsum[g]; g--; }
        int T = g*32;
        for (int k = 31; k >= 0; k--){
            acc += h[g*32 + k];
            if (acc >= MAXD){ T = g*32 + k; break; }
        }
        sT = T;
    }
    __syncthreads();
    int T = sT;
    int base = blockIdx.x * 2048;
    #pragma unroll
    for (int r = 0; r < 8; r++){
        int n = base + r*256 + tid;
        if (n < NPB){
            unsigned int sb = g_scores[b*NPB + n];
            if (score_bin(sb) >= T){
                int slot = atomicAdd(&g_ccount[b], 1);
                if (slot < CAP)
                    g_cand[b*CAP + slot] =
                        ((u64)sb << 28) | (u64)(0x0FFFFFFFu - (unsigned)n);
            }
        }
    }
}

// ---- 3. rank by enumeration (keys unique); prologue zeroes g_hist ----
__global__ __launch_bounds__(256) void k_rank(){
    int zid = (blockIdx.y*gridDim.x + blockIdx.x)*256 + threadIdx.x;
    for (int i = zid; i < NB*HBINS; i += gridDim.x*gridDim.y*256) g_hist[i] = 0;
    int b = blockIdx.y;
    int C = min(g_ccount[b], CAP);
    if (blockIdx.x*256 >= C) return;
    int idx = blockIdx.x*256 + threadIdx.x;
    u64 my = (idx < C) ? g_cand[b*CAP + idx] : 0ull;
    int rank = 0;
    __shared__ u64 tile[256];
    for (int t0 = 0; t0 < C; t0 += 256){
        int j = t0 + threadIdx.x;
        tile[threadIdx.x] = (j < C) ? g_cand[b*CAP + j] : 0ull;
        __syncthreads();
        int tn = min(256, C - t0);
        #pragma unroll 8
        for (int k = 0; k < tn; k++) rank += (tile[k] > my) ? 1 : 0;
        __syncthreads();
    }
    if (idx < C && rank < MAXD) g_topkeys[b*MAXD + rank] = my;
}

// ---- 4. gather: one WARP per detection (parallel scattered loads) ----
__global__ __launch_bounds__(256) void k_gather(Ptrs P){
    int cr = blockIdx.x, b = blockIdx.y, tid = threadIdx.x;
    int wid = tid >> 5, lane = tid & 31;
    if (cr == 0 && tid == 0) g_ccount[b] = 0;      // reset for next replay
    __shared__ float wmax[8];
    int j = cr*8 + wid;                            // det index in batch (< 1000)
    int t = b*MAXD + j;
    u64 key = g_topkeys[t];
    float score = __uint_as_float((unsigned int)(key >> 28));
    int n = 0x0FFFFFFF - (int)(key & 0x0FFFFFFFull);
    int mod = (n >= NPM) ? 1 : 0;
    int m = n - mod*NPM;
    int lvl,pos,w,st,hw; locate(m,lvl,pos,w,st,hw);
    const float* cls = P.p[mod*15 + lvl];
    const float* reg = P.p[mod*15 + 10 + lvl];
    int cbase = b*NCLS*hw + pos;
    int rbase = b*4*hw + pos;
    float sv = (lane < NCLS) ? sigm(cls[cbase + lane*hw]) : -INFINITY;
    float rv = (lane >= 20 && lane < 24) ? reg[rbase + (lane-20)*hw] : 0.0f;
    // lexicographic max (value, -index): == first-occurrence argmax
    float s = sv; int idx = lane;
    #pragma unroll
    for (int off = 16; off > 0; off >>= 1){
        float s2 = __shfl_down_sync(0xffffffffu, s, off);
        int   i2 = __shfl_down_sync(0xffffffffu, idx, off);
        if (s2 > s || (s2 == s && i2 < idx)){ s = s2; idx = i2; }
    }
    float r0 = __shfl_sync(0xffffffffu, rv, 20);
    float r1 = __shfl_sync(0xffffffffu, rv, 21);
    float r2 = __shfl_sync(0xffffffffu, rv, 22);
    float r3 = __shfl_sync(0xffffffffu, rv, 23);
    if (lane == 0){
        int y = pos / w, x = pos - y*w;
        float fx = (float)(x*st + (st>>1));
        float fy = (float)(y*st + (st>>1));
        float bx0 = __fsub_rn(fx, r0);
        float bx1 = __fsub_rn(fy, r1);
        float bx2 = __fadd_rn(fx, r2);
        float bx3 = __fadd_rn(fy, r3);
        int cl = idx + 1;
        unsigned char vl = (score >= 0.05f) ? 1 : 0;
        g_top_s[t] = score;
        g_top_c[t] = cl;
        g_top_b[4*t+0]=bx0; g_top_b[4*t+1]=bx1;
        g_top_b[4*t+2]=bx2; g_top_b[4*t+3]=bx3;
        g_valid[t] = vl;
        wmax[wid] = vl ? fmaxf(fmaxf(bx0,bx1), fmaxf(bx2,bx3)) : 0.0f;
    }
    __syncthreads();
    if (tid == 0){
        float mx = wmax[0];
        #pragma unroll
        for (int q = 1; q < 8; q++) mx = fmaxf(mx, wmax[q]);
        g_blkmax[b*GBLK + cr] = mx;
    }
}

// ---- 5. IoU mask with on-the-fly class offset (bit-identical op sequence) ----
__global__ __launch_bounds__(256) void k_mask(){
    int xt = c_tile_xt[blockIdx.x];
    int yg = c_tile_yg[blockIdx.x];
    int b  = blockIdx.y;
    __shared__ float sx1[256],sy1[256],sx2[256],sy2[256],sa[256];
    // mc1 from the gather block maxes (fmaxf order-exact under any order)
    float mm = g_blkmax[b*GBLK];
    #pragma unroll 5
    for (int q = 1; q < GBLK; q++) mm = fmaxf(mm, g_blkmax[b*GBLK + q]);
    float mc1 = __fadd_rn(mm, 1.0f);
    int jj = yg*256 + threadIdx.x;
    if (jj < MAXD){
        int tj = b*MAXD + jj;
        float off = __fmul_rn((float)g_top_c[tj], mc1);
        float x1 = __fadd_rn(g_top_b[4*tj+0], off);
        float y1 = __fadd_rn(g_top_b[4*tj+1], off);
        float x2 = __fadd_rn(g_top_b[4*tj+2], off);
        float y2 = __fadd_rn(g_top_b[4*tj+3], off);
        sx1[threadIdx.x]=x1; sy1[threadIdx.x]=y1;
        sx2[threadIdx.x]=x2; sy2[threadIdx.x]=y2;
        sa[threadIdx.x]=__fmul_rn(__fadd_rn(__fsub_rn(x2,x1),1.0f),
                                  __fadd_rn(__fsub_rn(y2,y1),1.0f));
    }
    __syncthreads();
    int il = threadIdx.x & 63;
    int wq = threadIdx.x >> 6;
    int i  = xt*64 + il;
    int w  = yg*4 + wq;
    if (i >= MAXD) return;
    if (w < (i >> 6)) return;
    int j0 = w*64;
    int jn = min(64, MAXD - j0);
    if (jn <= 0) return;
    int ti = b*MAXD + i;
    float offi = __fmul_rn((float)g_top_c[ti], mc1);
    float x1 = __fadd_rn(g_top_b[4*ti+0], offi);
    float y1 = __fadd_rn(g_top_b[4*ti+1], offi);
    float x2 = __fadd_rn(g_top_b[4*ti+2], offi);
    float y2 = __fadd_rn(g_top_b[4*ti+3], offi);
    float ai = __fmul_rn(__fadd_rn(__fsub_rn(x2,x1),1.0f),
                         __fadd_rn(__fsub_rn(y2,y1),1.0f));
    int sb = wq*64;
    u64 word = 0;
    for (int k=0;k<jn;k++){
        float xx1=fmaxf(x1,sx1[sb+k]), yy1=fmaxf(y1,sy1[sb+k]);
        float xx2=fminf(x2,sx2[sb+k]), yy2=fminf(y2,sy2[sb+k]);
        float iw=fmaxf(__fadd_rn(__fsub_rn(xx2,xx1),1.0f),0.0f);
        float ih=fmaxf(__fadd_rn(__fsub_rn(yy2,yy1),1.0f),0.0f);
        float inter=__fmul_rn(iw,ih);
        float denom=__fsub_rn(__fadd_rn(ai,sa[sb+k]),inter);
        float p = __fmul_rn(0.6f, denom);
        float e = __fmaf_rn(0.6f, denom, -p);                  // exact residual
        float s = __fadd_rn(e, __fmul_rn(0x1.0p-25f, denom));  // half-ulp shift
        float t = __fsub_rn(inter, p);
        bool sup;
        if (denom > 0.0f) sup = (t > s);
        else              sup = (denom == 0.0f && inter > 0.0f);
        if (sup) word |= (1ull<<k);
    }
    g_mask[((size_t)b*NPAD + i)*MASKW + w] = word;
}

// ---- 6. fused greedy scan + output write (1 block per batch) ----
__global__ void k_scan_out(float* __restrict__ out){
    extern __shared__ u64 sm[];                    // NPAD*MASKW words
    __shared__ u64 svm[MASKW];
    __shared__ u64 skeep[MASKW];
    int b = blockIdx.x, tid = threadIdx.x;
    const ulonglong2* src2 = (const ulonglong2*)&g_mask[(size_t)b*NPAD*MASKW];
    ulonglong2* sm2 = (ulonglong2*)sm;
    for (int i = tid; i < NPAD*MASKW/2; i += blockDim.x){
        ulonglong2 v = (i < MAXD*MASKW/2) ? src2[i] : make_ulonglong2(0ull,0ull);
        sm2[i] = v;
    }
    if (tid < MASKW){
        u64 w = 0;
        for (int i = 0; i < 64; i++){
            int j = tid*64 + i;
            if (j < MAXD && g_valid[b*MAXD + j]) w |= 1ull << i;
        }
        svm[tid] = w;
    }
    __syncthreads();
    if (tid < 32){
        int lane = tid;
        u64 removed = 0;
        for (int c = 0; c < MASKW; c++){
            u64 sup = __shfl_sync(0xffffffffu, removed, c);
            u64 vmc = svm[c];
            u64 kd = 0;
            #pragma unroll
            for (int q = 0; q < 4; q++){
                u64 dreg[16];
                #pragma unroll
                for (int r = 0; r < 16; r++) dreg[r] = sm[(c*64 + q*16 + r)*MASKW + c];
                #pragma unroll
                for (int r = 0; r < 16; r++){
                    int i = q*16 + r;
                    bool k = ((vmc >> i) & 1ull) && !((sup >> i) & 1ull);
                    if (k){ kd |= 1ull << i; sup |= dreg[r]; }
                }
            }
            if (lane == c) skeep[c] = kd;
            if (lane < MASKW){
                #pragma unroll
                for (int i = 0; i < 64; i++)
                    if ((kd >> i) & 1ull)
                        removed |= sm[(size_t)(c*64 + i)*MASKW + lane];
            }
        }
    }
    __syncthreads();
    for (int j = tid; j < MAXD; j += blockDim.x){
        int t = b*MAXD + j;
        int keep = (int)((skeep[j >> 6] >> (j & 63)) & 1ull);
        float kf = keep ? 1.0f : 0.0f;
        out[t]        = __fmul_rn(g_top_s[t], kf);
        out[TOPN + t] = keep ? (float)g_top_c[t] : 0.0f;
        float x1 = fminf(fmaxf(g_top_b[4*t+0],0.0f),1279.0f);
        float y1 = fminf(fmaxf(g_top_b[4*t+1],0.0f),1023.0f);
        float x2 = fminf(fmaxf(g_top_b[4*t+2],0.0f),1279.0f);
        float y2 = fminf(fmaxf(g_top_b[4*t+3],0.0f),1023.0f);
        out[2*TOPN + 4*t+0]=__fmul_rn(x1,kf);
        out[2*TOPN + 4*t+1]=__fmul_rn(y1,kf);
        out[2*TOPN + 4*t+2]=__fmul_rn(x2,kf);
        out[2*TOPN + 4*t+3]=__fmul_rn(y2,kf);
        out[6*TOPN + t]=kf;
    }
}

extern "C" void kernel_launch(void* const* d_in, const int* in_sizes, int n_in,
                              void* d_out, int out_size){
    Ptrs P;
    for (int i=0;i<30;i++) P.p[i] = (const float*)d_in[i];

    const int scan_smem = NPAD*MASKW*8;   // 131072 bytes
    cudaFuncSetAttribute(k_scan_out, cudaFuncAttributeMaxDynamicSharedMemorySize, scan_smem);

    k_decode  <<<dim3((NOCT + 255)/256, NB), 256>>>(P);
    k_compact <<<dim3(27, NB), 256>>>();
    k_rank    <<<dim3(CAP/256, NB), 256>>>();
    k_gather  <<<dim3(GBLK, NB), 256>>>(P);
    k_mask    <<<dim3(NTILES, NB), 256>>>();
    k_scan_out<<<NB, 256, scan_smem>>>((float*)d_out);
}